// round 13
// baseline (speedup 1.0000x reference)
#include <cuda_runtime.h>
#include <cuda_bf16.h>
#include <math.h>
#include <stdint.h>

#define NTOK   65536
#define MROWS  131072

// ===================== scratch (static device arrays) =========================
__device__ __nv_bfloat16 G_Xhi[67108864], G_Xlo[67108864];     // [m,512]
__device__ __nv_bfloat16 G_XThi[67108864], G_XTlo[67108864];   // [b][512][65536]
__device__ __nv_bfloat16 G_Vhi[67108864], G_Vlo[67108864];     // [m,512] v*illu
__device__ __nv_bfloat16 G_WvT_hi[262144], G_WvT_lo[262144];   // [c'][c]
__device__ __nv_bfloat16 G_WpT_hi[524288], G_WpT_lo[524288];   // [b][c'][e]
__device__ float S_vinp[67108864];          // x @ Wv (fp32, conv branch)
__device__ float S_v[67108864];             // conv1 output scratch
__device__ float g_XtX[2 * 512 * 512];
__device__ float g_T1[2 * 512 * 512];
__device__ float g_T2[2 * 512 * 512];
__device__ float g_G[2 * 8 * 64 * 64];
__device__ float g_Att[2 * 8 * 64 * 64];
__device__ float g_NQ[2 * 512];
__device__ float g_NK[2 * 512];

// upper-triangle pairs of the 4x4 tile grid
__constant__ int c_pi10[10] = {0,0,0,0,1,1,1,2,2,3};
__constant__ int c_pj10[10] = {0,1,2,3,1,2,3,2,3,3};

// ===================== portable PTX helpers ===================================
__device__ __forceinline__ uint32_t smem_u32(const void* p) {
    uint32_t a;
    asm("{ .reg .u64 t; cvta.to.shared.u64 t, %1; cvt.u32.u64 %0, t; }" : "=r"(a) : "l"(p));
    return a;
}
__device__ __forceinline__ void cp16(uint32_t dst, const void* src) {
    asm volatile("cp.async.cg.shared.global [%0], [%1], 16;" :: "r"(dst), "l"(src) : "memory");
}
#define CP_COMMIT() asm volatile("cp.async.commit_group;" ::: "memory")
#define CP_WAIT(n)  asm volatile("cp.async.wait_group %0;" :: "n"(n) : "memory")

#define SWZ(o) ((uint32_t)(o) ^ ((((uint32_t)(o)) >> 3) & 0x70u))

__device__ __forceinline__ void ldsm4(uint32_t (&r)[4], uint32_t a) {
    asm volatile("ldmatrix.sync.aligned.m8n8.x4.shared.b16 {%0,%1,%2,%3}, [%4];"
        : "=r"(r[0]), "=r"(r[1]), "=r"(r[2]), "=r"(r[3]) : "r"(a));
}
__device__ __forceinline__ void mma16816(float (&c)[4], const uint32_t (&a)[4],
                                         const uint32_t* b) {
    asm volatile("mma.sync.aligned.m16n8k16.row.col.f32.bf16.bf16.f32 "
        "{%0,%1,%2,%3}, {%4,%5,%6,%7}, {%8,%9}, {%0,%1,%2,%3};"
        : "+f"(c[0]), "+f"(c[1]), "+f"(c[2]), "+f"(c[3])
        : "r"(a[0]), "r"(a[1]), "r"(a[2]), "r"(a[3]), "r"(b[0]), "r"(b[1]));
}

__device__ __forceinline__ uint32_t pack_hl(float v0, float v1, uint32_t& lo) {
    __nv_bfloat16 h0 = __float2bfloat16(v0), h1 = __float2bfloat16(v1);
    __nv_bfloat16 l0 = __float2bfloat16(v0 - __bfloat162float(h0));
    __nv_bfloat16 l1 = __float2bfloat16(v1 - __bfloat162float(h1));
    lo = (uint32_t)__bfloat16_as_ushort(l0) | ((uint32_t)__bfloat16_as_ushort(l1) << 16);
    return (uint32_t)__bfloat16_as_ushort(h0) | ((uint32_t)__bfloat16_as_ushort(h1) << 16);
}

// ===================== HMMA GEMM core v3 ======================================
// CTA tile 128x128, K-chunk 64 bf16 (128B SW128 rows). 512 threads,
// 16 warps in 4x4 grid, warp tile 32x32. 3-stage cp.async ring (192KB smem).
#define STAGE 65536u
#define MM_SMEM (1024 + 3 * 65536)

__device__ __forceinline__ void load_chunk(uint32_t st, int tid,
    const __nv_bfloat16* ah, const __nv_bfloat16* al, size_t lda,
    const __nv_bfloat16* bh, const __nv_bfloat16* bl, size_t ldb)
{
#pragma unroll
    for (int i = 0; i < 2; ++i) {
        int item = tid + 512 * i;             // 0..1023
        int rr = item >> 3, cc = item & 7;    // 128 rows x 8 x 16B
        uint32_t so = SWZ(rr * 128 + cc * 16);
        cp16(st + so,           ah + (size_t)rr * lda + cc * 8);
        cp16(st + 16384u + so,  al + (size_t)rr * lda + cc * 8);
        cp16(st + 32768u + so,  bh + (size_t)rr * ldb + cc * 8);
        cp16(st + 49152u + so,  bl + (size_t)rr * ldb + cc * 8);
    }
    CP_COMMIT();
}

__device__ void mm_loop(const __nv_bfloat16* Ahi, const __nv_bfloat16* Alo, size_t lda,
                        const __nv_bfloat16* Bhi, const __nv_bfloat16* Blo, size_t ldb,
                        int kiters, char* smem_raw, float (&acc)[2][4][4])
{
    const int tid = threadIdx.x, lane = tid & 31, wid = tid >> 5;
    const int wm = wid >> 2, wn = wid & 3;
    uint32_t sb = (smem_u32(smem_raw) + 1023u) & ~1023u;

    load_chunk(sb, tid, Ahi, Alo, lda, Bhi, Blo, ldb);
    if (kiters > 1)
        load_chunk(sb + STAGE, tid, Ahi + 64, Alo + 64, lda, Bhi + 64, Blo + 64, ldb);

    const int a_row = wm * 32 + (lane & 15);
    const int a_kb  = (lane >> 4) << 4;
    const int g     = lane >> 3;
    const int b_row = wn * 32 + ((g >> 1) << 3) + (lane & 7);
    const int b_kb  = (g & 1) << 4;

    uint32_t stage_of[3] = {sb, sb + STAGE, sb + 2 * STAGE};
    int cur = 0;

    for (int k = 0; k < kiters; ++k) {
        uint32_t st = stage_of[cur];
        if (k + 1 < kiters) CP_WAIT(1); else CP_WAIT(0);
        __syncthreads();
        if (k + 2 < kiters) {
            int nxt = cur + 2; if (nxt >= 3) nxt -= 3;
            load_chunk(stage_of[nxt], tid,
                       Ahi + (size_t)(k + 2) * 64, Alo + (size_t)(k + 2) * 64, lda,
                       Bhi + (size_t)(k + 2) * 64, Blo + (size_t)(k + 2) * 64, ldb);
        }
#pragma unroll
        for (int ks = 0; ks < 4; ++ks) {
            uint32_t ah[2][4], al[2][4];
#pragma unroll
            for (int mt = 0; mt < 2; ++mt) {
                uint32_t so = SWZ((a_row + mt * 16) * 128 + ks * 32 + a_kb);
                ldsm4(ah[mt], st + so);
                ldsm4(al[mt], st + 16384u + so);
            }
            uint32_t bh[2][4], bl[2][4];
#pragma unroll
            for (int p = 0; p < 2; ++p) {
                uint32_t so = SWZ((b_row + p * 16) * 128 + ks * 32 + b_kb);
                ldsm4(bh[p], st + 32768u + so);
                ldsm4(bl[p], st + 49152u + so);
            }
#pragma unroll
            for (int mt = 0; mt < 2; ++mt)
#pragma unroll
                for (int nt = 0; nt < 4; ++nt) {
                    const uint32_t* bhp = &bh[nt >> 1][(nt & 1) * 2];
                    const uint32_t* blp = &bl[nt >> 1][(nt & 1) * 2];
                    mma16816(acc[mt][nt], ah[mt], bhp);   // hi*hi
                    mma16816(acc[mt][nt], ah[mt], blp);   // hi*lo
                    mma16816(acc[mt][nt], al[mt], bhp);   // lo*hi
                }
        }
        if (++cur == 3) cur = 0;
    }
}

// ---------------- v_inp = X @ Wv ; v = v_inp * illu ---------------------------
// grid (4 n-tiles, 1024 m-tiles): CTAs sharing an A tile are adjacent -> L2 reuse
__global__ __launch_bounds__(512, 1) void k_mm_v(const float* __restrict__ illu)
{
    extern __shared__ char smem[];
    float acc[2][4][4] = {};
    const int n0 = blockIdx.x * 128;
    const size_t m0 = (size_t)blockIdx.y * 128;
    mm_loop(G_Xhi + m0 * 512, G_Xlo + m0 * 512, 512,
            G_WvT_hi + (size_t)n0 * 512, G_WvT_lo + (size_t)n0 * 512, 512,
            8, smem, acc);
    const int lane = threadIdx.x & 31, wid = threadIdx.x >> 5;
    const int wm = wid >> 2, wn = wid & 3;
#pragma unroll
    for (int mt = 0; mt < 2; ++mt)
#pragma unroll
        for (int nt = 0; nt < 4; ++nt) {
            size_t row = m0 + wm * 32 + mt * 16 + (lane >> 2);
            int col = n0 + wn * 32 + nt * 8 + (lane & 3) * 2;
#pragma unroll
            for (int h = 0; h < 2; ++h) {
                size_t o = (row + h * 8) * 512 + col;
                float v0 = acc[mt][nt][h * 2 + 0], v1 = acc[mt][nt][h * 2 + 1];
                *(float2*)(S_vinp + o) = make_float2(v0, v1);
                float2 il = *(const float2*)(illu + o);
                uint32_t lo, hi = pack_hl(v0 * il.x, v1 * il.y, lo);
                *(uint32_t*)(G_Vhi + o) = hi;
                *(uint32_t*)(G_Vlo + o) = lo;
            }
        }
}

// ---------------- XtX upper-triangle tiles (128x128), split-K atomics ---------
__global__ __launch_bounds__(512, 1) void k_mm_xtx()
{
    extern __shared__ char smem[];
    float acc[2][4][4] = {};
    const int pr = blockIdx.x;                  // 10 upper-tri pairs
    const int ks = blockIdx.y;                  // 16 K-splits of 4096 tokens
    const int b  = blockIdx.z;
    const size_t i0 = (size_t)c_pi10[pr] * 128, j0 = (size_t)c_pj10[pr] * 128;
    const int mirror = (i0 != j0);
    const __nv_bfloat16* Th = G_XThi + (size_t)b * 512 * 65536 + (size_t)ks * 4096;
    const __nv_bfloat16* Tl = G_XTlo + (size_t)b * 512 * 65536 + (size_t)ks * 4096;
    mm_loop(Th + i0 * 65536, Tl + i0 * 65536, 65536,
            Th + j0 * 65536, Tl + j0 * 65536, 65536,
            64, smem, acc);
    const int lane = threadIdx.x & 31, wid = threadIdx.x >> 5;
    const int wm = wid >> 2, wn = wid & 3;
    float* C = g_XtX + b * 262144;
#pragma unroll
    for (int mt = 0; mt < 2; ++mt)
#pragma unroll
        for (int nt = 0; nt < 4; ++nt) {
            int row = (int)i0 + wm * 32 + mt * 16 + (lane >> 2);
            int col = (int)j0 + wn * 32 + nt * 8 + (lane & 3) * 2;
#pragma unroll
            for (int h = 0; h < 2; ++h) {
                float v0 = acc[mt][nt][h * 2 + 0], v1 = acc[mt][nt][h * 2 + 1];
                int r = row + h * 8;
                atomicAdd(&C[r * 512 + col],     v0);
                atomicAdd(&C[r * 512 + col + 1], v1);
                if (mirror) {
                    atomicAdd(&C[col * 512 + r],       v0);
                    atomicAdd(&C[(col + 1) * 512 + r], v1);
                }
            }
        }
}

// ---------------- out = v @ WpEff^T + bp --------------------------------------
__global__ __launch_bounds__(512, 1) void k_mm_out(const float* __restrict__ bp,
                                                   float* __restrict__ out)
{
    extern __shared__ char smem[];
    float acc[2][4][4] = {};
    const int n0 = blockIdx.x * 128;
    const size_t m0 = (size_t)blockIdx.y * 128;
    const int b = (m0 >= (size_t)NTOK) ? 1 : 0;
    mm_loop(G_Vhi + m0 * 512, G_Vlo + m0 * 512, 512,
            G_WpT_hi + (size_t)b * 262144 + (size_t)n0 * 512,
            G_WpT_lo + (size_t)b * 262144 + (size_t)n0 * 512, 512,
            8, smem, acc);
    const int lane = threadIdx.x & 31, wid = threadIdx.x >> 5;
    const int wm = wid >> 2, wn = wid & 3;
#pragma unroll
    for (int mt = 0; mt < 2; ++mt)
#pragma unroll
        for (int nt = 0; nt < 4; ++nt) {
            size_t row = m0 + wm * 32 + mt * 16 + (lane >> 2);
            int col = n0 + wn * 32 + nt * 8 + (lane & 3) * 2;
            float2 bb = *(const float2*)(bp + col);
#pragma unroll
            for (int h = 0; h < 2; ++h) {
                size_t o = (row + h * 8) * 512 + col;
                *(float2*)(out + o) = make_float2(acc[mt][nt][h * 2 + 0] + bb.x,
                                                  acc[mt][nt][h * 2 + 1] + bb.y);
            }
        }
}

// ---------------- convert X -> bf16 hi/lo, row-major + transposed -------------
__global__ __launch_bounds__(256) void k_cvt_x(const float* __restrict__ X)
{
    __shared__ float tile[64][65];
    const int n0 = blockIdx.x * 64;
    const int c0 = blockIdx.y * 64;
    const int tid = threadIdx.x;
#pragma unroll
    for (int i = 0; i < 4; ++i) {
        int item = tid + 256 * i;
        int r = item >> 4, c4 = item & 15;
        float4 v = *(const float4*)(X + (size_t)(n0 + r) * 512 + c0 + c4 * 4);
        tile[r][c4 * 4 + 0] = v.x; tile[r][c4 * 4 + 1] = v.y;
        tile[r][c4 * 4 + 2] = v.z; tile[r][c4 * 4 + 3] = v.w;
        uint32_t l0, l1;
        uint32_t h0 = pack_hl(v.x, v.y, l0), h1 = pack_hl(v.z, v.w, l1);
        size_t o = (size_t)(n0 + r) * 512 + c0 + c4 * 4;
        *(uint2*)(G_Xhi + o) = make_uint2(h0, h1);
        *(uint2*)(G_Xlo + o) = make_uint2(l0, l1);
    }
    __syncthreads();
    const int b = n0 >> 16;
    const int nin0 = n0 & 65535;
#pragma unroll
    for (int i = 0; i < 4; ++i) {
        int item = tid + 256 * i;
        int cc = item >> 4, t4 = item & 15;
        float v0 = tile[t4 * 4 + 0][cc], v1 = tile[t4 * 4 + 1][cc];
        float v2 = tile[t4 * 4 + 2][cc], v3 = tile[t4 * 4 + 3][cc];
        uint32_t l0, l1;
        uint32_t h0 = pack_hl(v0, v1, l0), h1 = pack_hl(v2, v3, l1);
        size_t o = (size_t)b * 512 * 65536 + (size_t)(c0 + cc) * 65536 + nin0 + t4 * 4;
        *(uint2*)(G_XThi + o) = make_uint2(h0, h1);
        *(uint2*)(G_XTlo + o) = make_uint2(l0, l1);
    }
}

// ---------------- convert Wv -> WvT hi/lo -------------------------------------
__global__ void k_cvt_w(const float* __restrict__ Wv)
{
    int o = blockIdx.x * 256 + threadIdx.x;       // [cp][c]
    int cp = o >> 9, c = o & 511;
    float v = Wv[(size_t)c * 512 + cp];
    __nv_bfloat16 h = __float2bfloat16(v);
    G_WvT_hi[o] = h;
    G_WvT_lo[o] = __float2bfloat16(v - __bfloat162float(h));
}

// ---------------- zero accumulated buffers ------------------------------------
__global__ void k_zero()
{
    int i = blockIdx.x * 256 + threadIdx.x;
    if (i < 2 * 512 * 512) { g_XtX[i] = 0.f; g_T1[i] = 0.f; g_T2[i] = 0.f; }
    if (i < 2 * 8 * 64 * 64) g_G[i] = 0.f;
}

// ===================== fp32 mid-chain =========================================
__device__ __forceinline__ void sgemm_core(const float* __restrict__ A,
                                           const float* __restrict__ Bw,
                                           int lda, int ldb, int kiters,
                                           float (&acc)[8][8])
{
    __shared__ float As[8][128];
    __shared__ float Bs[8][128];
    const int tid = threadIdx.x;
    const int lr = tid >> 1, lc = (tid & 1) << 2;
    const int wr = tid >> 5, wc = (tid & 31) << 2;
    const int ty = tid >> 4, tx = tid & 15;
    for (int kt = 0; kt < kiters; ++kt) {
        float4 a = *(const float4*)(A + (size_t)lr * lda + (kt << 3) + lc);
        float4 b = *(const float4*)(Bw + (size_t)((kt << 3) + wr) * ldb + wc);
        __syncthreads();
        As[lc + 0][lr] = a.x; As[lc + 1][lr] = a.y;
        As[lc + 2][lr] = a.z; As[lc + 3][lr] = a.w;
        *(float4*)&Bs[wr][wc] = b;
        __syncthreads();
#pragma unroll
        for (int kk = 0; kk < 8; ++kk) {
            float4 a0 = *(const float4*)&As[kk][ty << 3];
            float4 a1 = *(const float4*)&As[kk][(ty << 3) + 4];
            float4 b0 = *(const float4*)&Bs[kk][tx << 3];
            float4 b1 = *(const float4*)&Bs[kk][(tx << 3) + 4];
            float ra[8] = {a0.x, a0.y, a0.z, a0.w, a1.x, a1.y, a1.z, a1.w};
            float rb[8] = {b0.x, b0.y, b0.z, b0.w, b1.x, b1.y, b1.z, b1.w};
#pragma unroll
            for (int i = 0; i < 8; ++i)
#pragma unroll
                for (int j = 0; j < 8; ++j)
                    acc[i][j] = fmaf(ra[i], rb[j], acc[i][j]);
        }
    }
}

__global__ __launch_bounds__(256) void k_T(const float* __restrict__ Wq,
                                           const float* __restrict__ Wk)
{
    float acc[8][8] = {};
    const int col0 = blockIdx.x << 7;
    const int row0 = blockIdx.y << 7;
    const int z = blockIdx.z;
    const int b = z >> 4, mat = (z >> 3) & 1, kc = z & 7;
    const float* A  = g_XtX + b * (512 * 512) + (size_t)row0 * 512 + kc * 64;
    const float* Wm = (mat ? Wk : Wq) + (size_t)(kc * 64) * 512 + col0;
    sgemm_core(A, Wm, 512, 512, 8, acc);
    float* T = (mat ? g_T2 : g_T1) + b * (512 * 512);
    const int ty = threadIdx.x >> 4, tx = threadIdx.x & 15;
#pragma unroll
    for (int i = 0; i < 8; ++i)
#pragma unroll
        for (int j = 0; j < 8; ++j)
            atomicAdd(&T[(row0 + (ty << 3) + i) * 512 + col0 + (tx << 3) + j], acc[i][j]);
}

__global__ void k_normsq(const float* __restrict__ Wq, const float* __restrict__ Wk)
{
    const int b = blockIdx.x, mat = blockIdx.y;
    const float* Wm = mat ? Wk : Wq;
    const float* T  = (mat ? g_T2 : g_T1) + b * (512 * 512);
    const int j = threadIdx.x;
    float acc = 0.f;
    for (int k = 0; k < 512; ++k)
        acc = fmaf(Wm[k * 512 + j], T[k * 512 + j], acc);
    (mat ? g_NK : g_NQ)[b * 512 + j] = acc;
}

__global__ __launch_bounds__(256) void k_G(const float* __restrict__ Wk)
{
    __shared__ float Ks[64][64];
    __shared__ float Ts[64][64];
    const int kc = blockIdx.x, h = blockIdx.y, b = blockIdx.z;
    const int tid = threadIdx.x;
    for (int idx = tid; idx < 4096; idx += 256) {
        int kk = idx >> 6, col = idx & 63;
        Ks[kk][col] = Wk[(size_t)(kc * 64 + kk) * 512 + h * 64 + col];
        Ts[kk][col] = g_T1[b * (512 * 512) + (size_t)(kc * 64 + kk) * 512 + h * 64 + col];
    }
    __syncthreads();
    const int ty = tid >> 4, tx = tid & 15;
    float acc[4][4] = {};
    for (int kk = 0; kk < 64; ++kk) {
        float a[4], bb[4];
#pragma unroll
        for (int i = 0; i < 4; ++i) a[i]  = Ks[kk][ty * 4 + i];
#pragma unroll
        for (int j = 0; j < 4; ++j) bb[j] = Ts[kk][tx * 4 + j];
#pragma unroll
        for (int i = 0; i < 4; ++i)
#pragma unroll
            for (int j = 0; j < 4; ++j)
                acc[i][j] = fmaf(a[i], bb[j], acc[i][j]);
    }
    float* Gp = g_G + ((size_t)(b * 8 + h) << 12);
#pragma unroll
    for (int i = 0; i < 4; ++i)
#pragma unroll
        for (int j = 0; j < 4; ++j)
            atomicAdd(&Gp[(ty * 4 + i) * 64 + tx * 4 + j], acc[i][j]);
}

__global__ void k_softmax(const float* __restrict__ rescale)
{
    const int bh = blockIdx.x;
    const int b = bh >> 3, h = bh & 7;
    const int d = threadIdx.x;
    __shared__ float rnq[64];
    rnq[d] = 1.f / fmaxf(sqrtf(g_NQ[b * 512 + h * 64 + d]), 1e-12f);
    __syncthreads();
    const float rk = rescale[h] / fmaxf(sqrtf(g_NK[b * 512 + h * 64 + d]), 1e-12f);
    const float* Grow = g_G + ((size_t)bh << 12) + d * 64;
    float* Arow = g_Att + ((size_t)bh << 12) + d * 64;
    float mx = -1e30f;
    for (int e = 0; e < 64; ++e) mx = fmaxf(mx, Grow[e] * rk * rnq[e]);
    float sum = 0.f;
    for (int e = 0; e < 64; ++e) {
        float ex = expf(Grow[e] * rk * rnq[e] - mx);
        Arow[e] = ex;
        sum += ex;
    }
    float inv = 1.f / sum;
    for (int e = 0; e < 64; ++e) Arow[e] *= inv;
}

// WpEffT[b][c'][e] = sum_d Att[b,h,d,e] * Wp[h*64+d][c']  (bf16 hi/lo out)
__global__ __launch_bounds__(256) void k_wpeff(const float* __restrict__ Wp)
{
    __shared__ float Atts[64][64];
    __shared__ float Wps[64][128];
    const int ct = blockIdx.x, h = blockIdx.y, b = blockIdx.z;
    const int tid = threadIdx.x;
    for (int idx = tid; idx < 4096; idx += 256)
        Atts[idx >> 6][idx & 63] = g_Att[((size_t)(b * 8 + h) << 12) + idx];
    for (int idx = tid; idx < 8192; idx += 256) {
        int dd = idx >> 7, cc = idx & 127;
        Wps[dd][cc] = Wp[(size_t)(h * 64 + dd) * 512 + ct * 128 + cc];
    }
    __syncthreads();
    const int ty = tid >> 4, tx = tid & 15;
    float acc[4][8] = {};
    for (int dd = 0; dd < 64; ++dd) {
        float a[4], bb[8];
#pragma unroll
        for (int i = 0; i < 4; ++i) a[i]  = Atts[dd][ty * 4 + i];
#pragma unroll
        for (int j = 0; j < 8; ++j) bb[j] = Wps[dd][tx * 8 + j];
#pragma unroll
        for (int i = 0; i < 4; ++i)
#pragma unroll
            for (int j = 0; j < 8; ++j)
                acc[i][j] = fmaf(a[i], bb[j], acc[i][j]);
    }
#pragma unroll
    for (int i = 0; i < 4; ++i)
#pragma unroll
        for (int j = 0; j < 8; ++j) {
            float v = acc[i][j];
            int e = h * 64 + ty * 4 + i;
            int cpg = ct * 128 + tx * 8 + j;
            size_t o = (size_t)b * 262144 + (size_t)cpg * 512 + e;
            __nv_bfloat16 hh = __float2bfloat16(v);
            G_WpT_hi[o] = hh;
            G_WpT_lo[o] = __float2bfloat16(v - __bfloat162float(hh));
        }
}

// ---------------- depthwise conv 3x3 (NHWC) + exact GELU ----------------------
__global__ void k_conv1(const float* __restrict__ cw)
{
    __shared__ float kw[256 * 9];
    const int cbase9 = ((blockIdx.x & 1) << 8) * 9;
    for (int t = threadIdx.x; t < 2304; t += 256) kw[t] = cw[cbase9 + t];
    __syncthreads();
    const int idx = blockIdx.x * 256 + threadIdx.x;
    const int x = (idx >> 9) & 255, y = (idx >> 17) & 255;
    const float* w = &kw[threadIdx.x * 9];
    float acc = 0.f;
#pragma unroll
    for (int dy = -1; dy <= 1; ++dy) {
        int yy = y + dy; if ((unsigned)yy > 255u) continue;
#pragma unroll
        for (int dx = -1; dx <= 1; ++dx) {
            int xx = x + dx; if ((unsigned)xx > 255u) continue;
            acc = fmaf(S_vinp[idx + ((dy << 8) + dx) * 512], w[(dy + 1) * 3 + dx + 1], acc);
        }
    }
    S_v[idx] = 0.5f * acc * (1.f + erff(acc * 0.70710678118654752f));
}

__global__ void k_conv2(const float* __restrict__ cw, float* __restrict__ out)
{
    __shared__ float kw[256 * 9];
    const int cbase9 = ((blockIdx.x & 1) << 8) * 9;
    for (int t = threadIdx.x; t < 2304; t += 256) kw[t] = cw[cbase9 + t];
    __syncthreads();
    const int idx = blockIdx.x * 256 + threadIdx.x;
    const int x = (idx >> 9) & 255, y = (idx >> 17) & 255;
    const float* w = &kw[threadIdx.x * 9];
    float acc = 0.f;
#pragma unroll
    for (int dy = -1; dy <= 1; ++dy) {
        int yy = y + dy; if ((unsigned)yy > 255u) continue;
#pragma unroll
        for (int dx = -1; dx <= 1; ++dx) {
            int xx = x + dx; if ((unsigned)xx > 255u) continue;
            acc = fmaf(S_v[idx + ((dy << 8) + dx) * 512], w[(dy + 1) * 3 + dx + 1], acc);
        }
    }
    out[idx] += acc;
}

// ---------------- launcher -----------------------------------------------------
extern "C" void kernel_launch(void* const* d_in, const int* in_sizes, int n_in,
                              void* d_out, int out_size)
{
    const float* x    = (const float*)d_in[0];
    const float* illu = (const float*)d_in[1];
    const float* Wq   = (const float*)d_in[2];
    const float* Wk   = (const float*)d_in[3];
    const float* Wv   = (const float*)d_in[4];
    const float* resc = (const float*)d_in[5];
    const float* Wp   = (const float*)d_in[6];
    const float* bp   = (const float*)d_in[7];
    const float* cw1  = (const float*)d_in[8];
    const float* cw2  = (const float*)d_in[9];
    float* out = (float*)d_out;

    cudaFuncSetAttribute(k_mm_v,   cudaFuncAttributeMaxDynamicSharedMemorySize, MM_SMEM);
    cudaFuncSetAttribute(k_mm_xtx, cudaFuncAttributeMaxDynamicSharedMemorySize, MM_SMEM);
    cudaFuncSetAttribute(k_mm_out, cudaFuncAttributeMaxDynamicSharedMemorySize, MM_SMEM);

    k_zero<<<2048, 256>>>();
    k_cvt_x<<<dim3(2048, 8), 256>>>(x);
    k_cvt_w<<<1024, 256>>>(Wv);
    k_mm_v<<<dim3(4, 1024), 512, MM_SMEM>>>(illu);
    k_mm_xtx<<<dim3(10, 16, 2), 512, MM_SMEM>>>();
    k_T<<<dim3(4, 4, 32), 256>>>(Wq, Wk);
    k_normsq<<<dim3(2, 2), 512>>>(Wq, Wk);
    k_G<<<dim3(8, 8, 2), 256>>>(Wk);
    k_softmax<<<16, 64>>>(resc);
    k_wpeff<<<dim3(4, 8, 2), 256>>>(Wp);
    k_mm_out<<<dim3(4, 1024), 512, MM_SMEM>>>(bp, out);
    k_conv1<<<262144, 256>>>(cw1);
    k_conv2<<<262144, 256>>>(cw2, out);
}

// round 14
// speedup vs baseline: 1.0003x; 1.0003x over previous
#include <cuda_runtime.h>
#include <cuda_bf16.h>
#include <math.h>
#include <stdint.h>

#define NTOK   65536
#define MROWS  131072

// ===================== scratch (static device arrays) =========================
__device__ __nv_bfloat16 G_Xhi[67108864], G_Xlo[67108864];     // [m,512]
__device__ __nv_bfloat16 G_XThi[67108864], G_XTlo[67108864];   // [b][512][65536]
__device__ __nv_bfloat16 G_Vhi[67108864], G_Vlo[67108864];     // [m,512] v*illu
__device__ __nv_bfloat16 G_WvT_hi[262144], G_WvT_lo[262144];   // [c'][c]
__device__ __nv_bfloat16 G_WpT_hi[524288], G_WpT_lo[524288];   // [b][c'][e]
__device__ float S_vinp[67108864];          // x @ Wv (fp32, conv branch)
__device__ float S_v[67108864];             // conv1 output scratch
__device__ float g_XtX[2 * 512 * 512];
__device__ float g_T1[2 * 512 * 512];
__device__ float g_T2[2 * 512 * 512];
__device__ float g_G[2 * 8 * 64 * 64];
__device__ float g_Att[2 * 8 * 64 * 64];
__device__ float g_NQ[2 * 512];
__device__ float g_NK[2 * 512];

// upper-triangle pairs of the 4x4 tile grid
__constant__ int c_pi10[10] = {0,0,0,0,1,1,1,2,2,3};
__constant__ int c_pj10[10] = {0,1,2,3,1,2,3,2,3,3};

// ===================== portable PTX helpers ===================================
__device__ __forceinline__ uint32_t smem_u32(const void* p) {
    uint32_t a;
    asm("{ .reg .u64 t; cvta.to.shared.u64 t, %1; cvt.u32.u64 %0, t; }" : "=r"(a) : "l"(p));
    return a;
}
__device__ __forceinline__ void cp16(uint32_t dst, const void* src) {
    asm volatile("cp.async.cg.shared.global [%0], [%1], 16;" :: "r"(dst), "l"(src) : "memory");
}
#define CP_COMMIT() asm volatile("cp.async.commit_group;" ::: "memory")
#define CP_WAIT(n)  asm volatile("cp.async.wait_group %0;" :: "n"(n) : "memory")

#define SWZ(o) ((uint32_t)(o) ^ ((((uint32_t)(o)) >> 3) & 0x70u))

__device__ __forceinline__ void ldsm4(uint32_t (&r)[4], uint32_t a) {
    asm volatile("ldmatrix.sync.aligned.m8n8.x4.shared.b16 {%0,%1,%2,%3}, [%4];"
        : "=r"(r[0]), "=r"(r[1]), "=r"(r[2]), "=r"(r[3]) : "r"(a));
}
__device__ __forceinline__ void mma16816(float (&c)[4], const uint32_t (&a)[4],
                                         const uint32_t* b) {
    asm volatile("mma.sync.aligned.m16n8k16.row.col.f32.bf16.bf16.f32 "
        "{%0,%1,%2,%3}, {%4,%5,%6,%7}, {%8,%9}, {%0,%1,%2,%3};"
        : "+f"(c[0]), "+f"(c[1]), "+f"(c[2]), "+f"(c[3])
        : "r"(a[0]), "r"(a[1]), "r"(a[2]), "r"(a[3]), "r"(b[0]), "r"(b[1]));
}

__device__ __forceinline__ uint32_t pack_hl(float v0, float v1, uint32_t& lo) {
    __nv_bfloat16 h0 = __float2bfloat16(v0), h1 = __float2bfloat16(v1);
    __nv_bfloat16 l0 = __float2bfloat16(v0 - __bfloat162float(h0));
    __nv_bfloat16 l1 = __float2bfloat16(v1 - __bfloat162float(h1));
    lo = (uint32_t)__bfloat16_as_ushort(l0) | ((uint32_t)__bfloat16_as_ushort(l1) << 16);
    return (uint32_t)__bfloat16_as_ushort(h0) | ((uint32_t)__bfloat16_as_ushort(h1) << 16);
}

// ===================== HMMA GEMM core v3 ======================================
// CTA tile 128x128, K-chunk 64 bf16 (128B SW128 rows). 512 threads,
// 16 warps in 4x4 grid, warp tile 32x32. 3-stage cp.async ring (192KB smem).
#define STAGE 65536u
#define MM_SMEM (1024 + 3 * 65536)

__device__ __forceinline__ void load_chunk(uint32_t st, int tid,
    const __nv_bfloat16* ah, const __nv_bfloat16* al, size_t lda,
    const __nv_bfloat16* bh, const __nv_bfloat16* bl, size_t ldb)
{
#pragma unroll
    for (int i = 0; i < 2; ++i) {
        int item = tid + 512 * i;             // 0..1023
        int rr = item >> 3, cc = item & 7;    // 128 rows x 8 x 16B
        uint32_t so = SWZ(rr * 128 + cc * 16);
        cp16(st + so,           ah + (size_t)rr * lda + cc * 8);
        cp16(st + 16384u + so,  al + (size_t)rr * lda + cc * 8);
        cp16(st + 32768u + so,  bh + (size_t)rr * ldb + cc * 8);
        cp16(st + 49152u + so,  bl + (size_t)rr * ldb + cc * 8);
    }
    CP_COMMIT();
}

__device__ void mm_loop(const __nv_bfloat16* Ahi, const __nv_bfloat16* Alo, size_t lda,
                        const __nv_bfloat16* Bhi, const __nv_bfloat16* Blo, size_t ldb,
                        int kiters, char* smem_raw, float (&acc)[2][4][4])
{
    const int tid = threadIdx.x, lane = tid & 31, wid = tid >> 5;
    const int wm = wid >> 2, wn = wid & 3;
    uint32_t sb = (smem_u32(smem_raw) + 1023u) & ~1023u;

    load_chunk(sb, tid, Ahi, Alo, lda, Bhi, Blo, ldb);
    if (kiters > 1)
        load_chunk(sb + STAGE, tid, Ahi + 64, Alo + 64, lda, Bhi + 64, Blo + 64, ldb);

    const int a_row = wm * 32 + (lane & 15);
    const int a_kb  = (lane >> 4) << 4;
    const int g     = lane >> 3;
    const int b_row = wn * 32 + ((g >> 1) << 3) + (lane & 7);
    const int b_kb  = (g & 1) << 4;

    uint32_t stage_of[3] = {sb, sb + STAGE, sb + 2 * STAGE};
    int cur = 0;

    for (int k = 0; k < kiters; ++k) {
        uint32_t st = stage_of[cur];
        if (k + 1 < kiters) CP_WAIT(1); else CP_WAIT(0);
        __syncthreads();
        if (k + 2 < kiters) {
            int nxt = cur + 2; if (nxt >= 3) nxt -= 3;
            load_chunk(stage_of[nxt], tid,
                       Ahi + (size_t)(k + 2) * 64, Alo + (size_t)(k + 2) * 64, lda,
                       Bhi + (size_t)(k + 2) * 64, Blo + (size_t)(k + 2) * 64, ldb);
        }
#pragma unroll
        for (int ks = 0; ks < 4; ++ks) {
            uint32_t ah[2][4], al[2][4];
#pragma unroll
            for (int mt = 0; mt < 2; ++mt) {
                uint32_t so = SWZ((a_row + mt * 16) * 128 + ks * 32 + a_kb);
                ldsm4(ah[mt], st + so);
                ldsm4(al[mt], st + 16384u + so);
            }
            uint32_t bh[2][4], bl[2][4];
#pragma unroll
            for (int p = 0; p < 2; ++p) {
                uint32_t so = SWZ((b_row + p * 16) * 128 + ks * 32 + b_kb);
                ldsm4(bh[p], st + 32768u + so);
                ldsm4(bl[p], st + 49152u + so);
            }
#pragma unroll
            for (int mt = 0; mt < 2; ++mt)
#pragma unroll
                for (int nt = 0; nt < 4; ++nt) {
                    const uint32_t* bhp = &bh[nt >> 1][(nt & 1) * 2];
                    const uint32_t* blp = &bl[nt >> 1][(nt & 1) * 2];
                    mma16816(acc[mt][nt], ah[mt], bhp);   // hi*hi
                    mma16816(acc[mt][nt], ah[mt], blp);   // hi*lo
                    mma16816(acc[mt][nt], al[mt], bhp);   // lo*hi
                }
        }
        if (++cur == 3) cur = 0;
    }
}

// ---------------- v_inp = X @ Wv ; v = v_inp * illu ---------------------------
// grid (4 n-tiles, 1024 m-tiles): CTAs sharing an A tile are adjacent -> L2 reuse
__global__ __launch_bounds__(512, 1) void k_mm_v(const float* __restrict__ illu)
{
    extern __shared__ char smem[];
    float acc[2][4][4] = {};
    const int n0 = blockIdx.x * 128;
    const size_t m0 = (size_t)blockIdx.y * 128;
    mm_loop(G_Xhi + m0 * 512, G_Xlo + m0 * 512, 512,
            G_WvT_hi + (size_t)n0 * 512, G_WvT_lo + (size_t)n0 * 512, 512,
            8, smem, acc);
    const int lane = threadIdx.x & 31, wid = threadIdx.x >> 5;
    const int wm = wid >> 2, wn = wid & 3;
#pragma unroll
    for (int mt = 0; mt < 2; ++mt)
#pragma unroll
        for (int nt = 0; nt < 4; ++nt) {
            size_t row = m0 + wm * 32 + mt * 16 + (lane >> 2);
            int col = n0 + wn * 32 + nt * 8 + (lane & 3) * 2;
#pragma unroll
            for (int h = 0; h < 2; ++h) {
                size_t o = (row + h * 8) * 512 + col;
                float v0 = acc[mt][nt][h * 2 + 0], v1 = acc[mt][nt][h * 2 + 1];
                *(float2*)(S_vinp + o) = make_float2(v0, v1);
                float2 il = *(const float2*)(illu + o);
                uint32_t lo, hi = pack_hl(v0 * il.x, v1 * il.y, lo);
                *(uint32_t*)(G_Vhi + o) = hi;
                *(uint32_t*)(G_Vlo + o) = lo;
            }
        }
}

// ---------------- XtX upper-triangle tiles (128x128), split-K atomics ---------
__global__ __launch_bounds__(512, 1) void k_mm_xtx()
{
    extern __shared__ char smem[];
    float acc[2][4][4] = {};
    const int pr = blockIdx.x;                  // 10 upper-tri pairs
    const int ks = blockIdx.y;                  // 16 K-splits of 4096 tokens
    const int b  = blockIdx.z;
    const size_t i0 = (size_t)c_pi10[pr] * 128, j0 = (size_t)c_pj10[pr] * 128;
    const int mirror = (i0 != j0);
    const __nv_bfloat16* Th = G_XThi + (size_t)b * 512 * 65536 + (size_t)ks * 4096;
    const __nv_bfloat16* Tl = G_XTlo + (size_t)b * 512 * 65536 + (size_t)ks * 4096;
    mm_loop(Th + i0 * 65536, Tl + i0 * 65536, 65536,
            Th + j0 * 65536, Tl + j0 * 65536, 65536,
            64, smem, acc);
    const int lane = threadIdx.x & 31, wid = threadIdx.x >> 5;
    const int wm = wid >> 2, wn = wid & 3;
    float* C = g_XtX + b * 262144;
#pragma unroll
    for (int mt = 0; mt < 2; ++mt)
#pragma unroll
        for (int nt = 0; nt < 4; ++nt) {
            int row = (int)i0 + wm * 32 + mt * 16 + (lane >> 2);
            int col = (int)j0 + wn * 32 + nt * 8 + (lane & 3) * 2;
#pragma unroll
            for (int h = 0; h < 2; ++h) {
                float v0 = acc[mt][nt][h * 2 + 0], v1 = acc[mt][nt][h * 2 + 1];
                int r = row + h * 8;
                atomicAdd(&C[r * 512 + col],     v0);
                atomicAdd(&C[r * 512 + col + 1], v1);
                if (mirror) {
                    atomicAdd(&C[col * 512 + r],       v0);
                    atomicAdd(&C[(col + 1) * 512 + r], v1);
                }
            }
        }
}

// ---------------- out = v @ WpEff^T + bp --------------------------------------
__global__ __launch_bounds__(512, 1) void k_mm_out(const float* __restrict__ bp,
                                                   float* __restrict__ out)
{
    extern __shared__ char smem[];
    float acc[2][4][4] = {};
    const int n0 = blockIdx.x * 128;
    const size_t m0 = (size_t)blockIdx.y * 128;
    const int b = (m0 >= (size_t)NTOK) ? 1 : 0;
    mm_loop(G_Vhi + m0 * 512, G_Vlo + m0 * 512, 512,
            G_WpT_hi + (size_t)b * 262144 + (size_t)n0 * 512,
            G_WpT_lo + (size_t)b * 262144 + (size_t)n0 * 512, 512,
            8, smem, acc);
    const int lane = threadIdx.x & 31, wid = threadIdx.x >> 5;
    const int wm = wid >> 2, wn = wid & 3;
#pragma unroll
    for (int mt = 0; mt < 2; ++mt)
#pragma unroll
        for (int nt = 0; nt < 4; ++nt) {
            size_t row = m0 + wm * 32 + mt * 16 + (lane >> 2);
            int col = n0 + wn * 32 + nt * 8 + (lane & 3) * 2;
            float2 bb = *(const float2*)(bp + col);
#pragma unroll
            for (int h = 0; h < 2; ++h) {
                size_t o = (row + h * 8) * 512 + col;
                *(float2*)(out + o) = make_float2(acc[mt][nt][h * 2 + 0] + bb.x,
                                                  acc[mt][nt][h * 2 + 1] + bb.y);
            }
        }
}

// ---------------- convert X -> bf16 hi/lo, row-major + transposed -------------
__global__ __launch_bounds__(256) void k_cvt_x(const float* __restrict__ X)
{
    __shared__ float tile[64][65];
    const int n0 = blockIdx.x * 64;
    const int c0 = blockIdx.y * 64;
    const int tid = threadIdx.x;
#pragma unroll
    for (int i = 0; i < 4; ++i) {
        int item = tid + 256 * i;
        int r = item >> 4, c4 = item & 15;
        float4 v = *(const float4*)(X + (size_t)(n0 + r) * 512 + c0 + c4 * 4);
        tile[r][c4 * 4 + 0] = v.x; tile[r][c4 * 4 + 1] = v.y;
        tile[r][c4 * 4 + 2] = v.z; tile[r][c4 * 4 + 3] = v.w;
        uint32_t l0, l1;
        uint32_t h0 = pack_hl(v.x, v.y, l0), h1 = pack_hl(v.z, v.w, l1);
        size_t o = (size_t)(n0 + r) * 512 + c0 + c4 * 4;
        *(uint2*)(G_Xhi + o) = make_uint2(h0, h1);
        *(uint2*)(G_Xlo + o) = make_uint2(l0, l1);
    }
    __syncthreads();
    const int b = n0 >> 16;
    const int nin0 = n0 & 65535;
#pragma unroll
    for (int i = 0; i < 4; ++i) {
        int item = tid + 256 * i;
        int cc = item >> 4, t4 = item & 15;
        float v0 = tile[t4 * 4 + 0][cc], v1 = tile[t4 * 4 + 1][cc];
        float v2 = tile[t4 * 4 + 2][cc], v3 = tile[t4 * 4 + 3][cc];
        uint32_t l0, l1;
        uint32_t h0 = pack_hl(v0, v1, l0), h1 = pack_hl(v2, v3, l1);
        size_t o = (size_t)b * 512 * 65536 + (size_t)(c0 + cc) * 65536 + nin0 + t4 * 4;
        *(uint2*)(G_XThi + o) = make_uint2(h0, h1);
        *(uint2*)(G_XTlo + o) = make_uint2(l0, l1);
    }
}

// ---------------- convert Wv -> WvT hi/lo -------------------------------------
__global__ void k_cvt_w(const float* __restrict__ Wv)
{
    int o = blockIdx.x * 256 + threadIdx.x;       // [cp][c]
    int cp = o >> 9, c = o & 511;
    float v = Wv[(size_t)c * 512 + cp];
    __nv_bfloat16 h = __float2bfloat16(v);
    G_WvT_hi[o] = h;
    G_WvT_lo[o] = __float2bfloat16(v - __bfloat162float(h));
}

// ---------------- zero accumulated buffers ------------------------------------
__global__ void k_zero()
{
    int i = blockIdx.x * 256 + threadIdx.x;
    if (i < 2 * 512 * 512) { g_XtX[i] = 0.f; g_T1[i] = 0.f; g_T2[i] = 0.f; }
    if (i < 2 * 8 * 64 * 64) g_G[i] = 0.f;
}

// ===================== fp32 mid-chain =========================================
__device__ __forceinline__ void sgemm_core(const float* __restrict__ A,
                                           const float* __restrict__ Bw,
                                           int lda, int ldb, int kiters,
                                           float (&acc)[8][8])
{
    __shared__ float As[8][128];
    __shared__ float Bs[8][128];
    const int tid = threadIdx.x;
    const int lr = tid >> 1, lc = (tid & 1) << 2;
    const int wr = tid >> 5, wc = (tid & 31) << 2;
    const int ty = tid >> 4, tx = tid & 15;
    for (int kt = 0; kt < kiters; ++kt) {
        float4 a = *(const float4*)(A + (size_t)lr * lda + (kt << 3) + lc);
        float4 b = *(const float4*)(Bw + (size_t)((kt << 3) + wr) * ldb + wc);
        __syncthreads();
        As[lc + 0][lr] = a.x; As[lc + 1][lr] = a.y;
        As[lc + 2][lr] = a.z; As[lc + 3][lr] = a.w;
        *(float4*)&Bs[wr][wc] = b;
        __syncthreads();
#pragma unroll
        for (int kk = 0; kk < 8; ++kk) {
            float4 a0 = *(const float4*)&As[kk][ty << 3];
            float4 a1 = *(const float4*)&As[kk][(ty << 3) + 4];
            float4 b0 = *(const float4*)&Bs[kk][tx << 3];
            float4 b1 = *(const float4*)&Bs[kk][(tx << 3) + 4];
            float ra[8] = {a0.x, a0.y, a0.z, a0.w, a1.x, a1.y, a1.z, a1.w};
            float rb[8] = {b0.x, b0.y, b0.z, b0.w, b1.x, b1.y, b1.z, b1.w};
#pragma unroll
            for (int i = 0; i < 8; ++i)
#pragma unroll
                for (int j = 0; j < 8; ++j)
                    acc[i][j] = fmaf(ra[i], rb[j], acc[i][j]);
        }
    }
}

__global__ __launch_bounds__(256) void k_T(const float* __restrict__ Wq,
                                           const float* __restrict__ Wk)
{
    float acc[8][8] = {};
    const int col0 = blockIdx.x << 7;
    const int row0 = blockIdx.y << 7;
    const int z = blockIdx.z;
    const int b = z >> 4, mat = (z >> 3) & 1, kc = z & 7;
    const float* A  = g_XtX + b * (512 * 512) + (size_t)row0 * 512 + kc * 64;
    const float* Wm = (mat ? Wk : Wq) + (size_t)(kc * 64) * 512 + col0;
    sgemm_core(A, Wm, 512, 512, 8, acc);
    float* T = (mat ? g_T2 : g_T1) + b * (512 * 512);
    const int ty = threadIdx.x >> 4, tx = threadIdx.x & 15;
#pragma unroll
    for (int i = 0; i < 8; ++i)
#pragma unroll
        for (int j = 0; j < 8; ++j)
            atomicAdd(&T[(row0 + (ty << 3) + i) * 512 + col0 + (tx << 3) + j], acc[i][j]);
}

__global__ void k_normsq(const float* __restrict__ Wq, const float* __restrict__ Wk)
{
    const int b = blockIdx.x, mat = blockIdx.y;
    const float* Wm = mat ? Wk : Wq;
    const float* T  = (mat ? g_T2 : g_T1) + b * (512 * 512);
    const int j = threadIdx.x;
    float acc = 0.f;
    for (int k = 0; k < 512; ++k)
        acc = fmaf(Wm[k * 512 + j], T[k * 512 + j], acc);
    (mat ? g_NK : g_NQ)[b * 512 + j] = acc;
}

__global__ __launch_bounds__(256) void k_G(const float* __restrict__ Wk)
{
    __shared__ float Ks[64][64];
    __shared__ float Ts[64][64];
    const int kc = blockIdx.x, h = blockIdx.y, b = blockIdx.z;
    const int tid = threadIdx.x;
    for (int idx = tid; idx < 4096; idx += 256) {
        int kk = idx >> 6, col = idx & 63;
        Ks[kk][col] = Wk[(size_t)(kc * 64 + kk) * 512 + h * 64 + col];
        Ts[kk][col] = g_T1[b * (512 * 512) + (size_t)(kc * 64 + kk) * 512 + h * 64 + col];
    }
    __syncthreads();
    const int ty = tid >> 4, tx = tid & 15;
    float acc[4][4] = {};
    for (int kk = 0; kk < 64; ++kk) {
        float a[4], bb[4];
#pragma unroll
        for (int i = 0; i < 4; ++i) a[i]  = Ks[kk][ty * 4 + i];
#pragma unroll
        for (int j = 0; j < 4; ++j) bb[j] = Ts[kk][tx * 4 + j];
#pragma unroll
        for (int i = 0; i < 4; ++i)
#pragma unroll
            for (int j = 0; j < 4; ++j)
                acc[i][j] = fmaf(a[i], bb[j], acc[i][j]);
    }
    float* Gp = g_G + ((size_t)(b * 8 + h) << 12);
#pragma unroll
    for (int i = 0; i < 4; ++i)
#pragma unroll
        for (int j = 0; j < 4; ++j)
            atomicAdd(&Gp[(ty * 4 + i) * 64 + tx * 4 + j], acc[i][j]);
}

__global__ void k_softmax(const float* __restrict__ rescale)
{
    const int bh = blockIdx.x;
    const int b = bh >> 3, h = bh & 7;
    const int d = threadIdx.x;
    __shared__ float rnq[64];
    rnq[d] = 1.f / fmaxf(sqrtf(g_NQ[b * 512 + h * 64 + d]), 1e-12f);
    __syncthreads();
    const float rk = rescale[h] / fmaxf(sqrtf(g_NK[b * 512 + h * 64 + d]), 1e-12f);
    const float* Grow = g_G + ((size_t)bh << 12) + d * 64;
    float* Arow = g_Att + ((size_t)bh << 12) + d * 64;
    float mx = -1e30f;
    for (int e = 0; e < 64; ++e) mx = fmaxf(mx, Grow[e] * rk * rnq[e]);
    float sum = 0.f;
    for (int e = 0; e < 64; ++e) {
        float ex = expf(Grow[e] * rk * rnq[e] - mx);
        Arow[e] = ex;
        sum += ex;
    }
    float inv = 1.f / sum;
    for (int e = 0; e < 64; ++e) Arow[e] *= inv;
}

// WpEffT[b][c'][e] = sum_d Att[b,h,d,e] * Wp[h*64+d][c']  (bf16 hi/lo out)
__global__ __launch_bounds__(256) void k_wpeff(const float* __restrict__ Wp)
{
    __shared__ float Atts[64][64];
    __shared__ float Wps[64][128];
    const int ct = blockIdx.x, h = blockIdx.y, b = blockIdx.z;
    const int tid = threadIdx.x;
    for (int idx = tid; idx < 4096; idx += 256)
        Atts[idx >> 6][idx & 63] = g_Att[((size_t)(b * 8 + h) << 12) + idx];
    for (int idx = tid; idx < 8192; idx += 256) {
        int dd = idx >> 7, cc = idx & 127;
        Wps[dd][cc] = Wp[(size_t)(h * 64 + dd) * 512 + ct * 128 + cc];
    }
    __syncthreads();
    const int ty = tid >> 4, tx = tid & 15;
    float acc[4][8] = {};
    for (int dd = 0; dd < 64; ++dd) {
        float a[4], bb[8];
#pragma unroll
        for (int i = 0; i < 4; ++i) a[i]  = Atts[dd][ty * 4 + i];
#pragma unroll
        for (int j = 0; j < 8; ++j) bb[j] = Wps[dd][tx * 8 + j];
#pragma unroll
        for (int i = 0; i < 4; ++i)
#pragma unroll
            for (int j = 0; j < 8; ++j)
                acc[i][j] = fmaf(a[i], bb[j], acc[i][j]);
    }
#pragma unroll
    for (int i = 0; i < 4; ++i)
#pragma unroll
        for (int j = 0; j < 8; ++j) {
            float v = acc[i][j];
            int e = h * 64 + ty * 4 + i;
            int cpg = ct * 128 + tx * 8 + j;
            size_t o = (size_t)b * 262144 + (size_t)cpg * 512 + e;
            __nv_bfloat16 hh = __float2bfloat16(v);
            G_WpT_hi[o] = hh;
            G_WpT_lo[o] = __float2bfloat16(v - __bfloat162float(hh));
        }
}

// ---------------- depthwise conv 3x3 (NHWC) + exact GELU ----------------------
__global__ void k_conv1(const float* __restrict__ cw)
{
    __shared__ float kw[256 * 9];
    const int cbase9 = ((blockIdx.x & 1) << 8) * 9;
    for (int t = threadIdx.x; t < 2304; t += 256) kw[t] = cw[cbase9 + t];
    __syncthreads();
    const int idx = blockIdx.x * 256 + threadIdx.x;
    const int x = (idx >> 9) & 255, y = (idx >> 17) & 255;
    const float* w = &kw[threadIdx.x * 9];
    float acc = 0.f;
#pragma unroll
    for (int dy = -1; dy <= 1; ++dy) {
        int yy = y + dy; if ((unsigned)yy > 255u) continue;
#pragma unroll
        for (int dx = -1; dx <= 1; ++dx) {
            int xx = x + dx; if ((unsigned)xx > 255u) continue;
            acc = fmaf(S_vinp[idx + ((dy << 8) + dx) * 512], w[(dy + 1) * 3 + dx + 1], acc);
        }
    }
    S_v[idx] = 0.5f * acc * (1.f + erff(acc * 0.70710678118654752f));
}

__global__ void k_conv2(const float* __restrict__ cw, float* __restrict__ out)
{
    __shared__ float kw[256 * 9];
    const int cbase9 = ((blockIdx.x & 1) << 8) * 9;
    for (int t = threadIdx.x; t < 2304; t += 256) kw[t] = cw[cbase9 + t];
    __syncthreads();
    const int idx = blockIdx.x * 256 + threadIdx.x;
    const int x = (idx >> 9) & 255, y = (idx >> 17) & 255;
    const float* w = &kw[threadIdx.x * 9];
    float acc = 0.f;
#pragma unroll
    for (int dy = -1; dy <= 1; ++dy) {
        int yy = y + dy; if ((unsigned)yy > 255u) continue;
#pragma unroll
        for (int dx = -1; dx <= 1; ++dx) {
            int xx = x + dx; if ((unsigned)xx > 255u) continue;
            acc = fmaf(S_v[idx + ((dy << 8) + dx) * 512], w[(dy + 1) * 3 + dx + 1], acc);
        }
    }
    out[idx] += acc;
}

// ---------------- launcher -----------------------------------------------------
extern "C" void kernel_launch(void* const* d_in, const int* in_sizes, int n_in,
                              void* d_out, int out_size)
{
    const float* x    = (const float*)d_in[0];
    const float* illu = (const float*)d_in[1];
    const float* Wq   = (const float*)d_in[2];
    const float* Wk   = (const float*)d_in[3];
    const float* Wv   = (const float*)d_in[4];
    const float* resc = (const float*)d_in[5];
    const float* Wp   = (const float*)d_in[6];
    const float* bp   = (const float*)d_in[7];
    const float* cw1  = (const float*)d_in[8];
    const float* cw2  = (const float*)d_in[9];
    float* out = (float*)d_out;

    cudaFuncSetAttribute(k_mm_v,   cudaFuncAttributeMaxDynamicSharedMemorySize, MM_SMEM);
    cudaFuncSetAttribute(k_mm_xtx, cudaFuncAttributeMaxDynamicSharedMemorySize, MM_SMEM);
    cudaFuncSetAttribute(k_mm_out, cudaFuncAttributeMaxDynamicSharedMemorySize, MM_SMEM);

    k_zero<<<2048, 256>>>();
    k_cvt_x<<<dim3(2048, 8), 256>>>(x);
    k_cvt_w<<<1024, 256>>>(Wv);
    k_mm_v<<<dim3(4, 1024), 512, MM_SMEM>>>(illu);
    k_mm_xtx<<<dim3(10, 16, 2), 512, MM_SMEM>>>();
    k_T<<<dim3(4, 4, 32), 256>>>(Wq, Wk);
    k_normsq<<<dim3(2, 2), 512>>>(Wq, Wk);
    k_G<<<dim3(8, 8, 2), 256>>>(Wk);
    k_softmax<<<16, 64>>>(resc);
    k_wpeff<<<dim3(4, 8, 2), 256>>>(Wp);
    k_mm_out<<<dim3(4, 1024), 512, MM_SMEM>>>(bp, out);
    k_conv1<<<262144, 256>>>(cw1);
    k_conv2<<<262144, 256>>>(cw2, out);
}

// round 15
// speedup vs baseline: 1.0015x; 1.0013x over previous
#include <cuda_runtime.h>
#include <cuda_bf16.h>
#include <math.h>
#include <stdint.h>

#define NTOK   65536
#define MROWS  131072

// ===================== scratch (static device arrays) =========================
__device__ __nv_bfloat16 G_Xhi[67108864], G_Xlo[67108864];     // [m,512]
__device__ __nv_bfloat16 G_XThi[67108864], G_XTlo[67108864];   // [b][512][65536]
__device__ __nv_bfloat16 G_Vhi[67108864], G_Vlo[67108864];     // [m,512] v*illu
__device__ __nv_bfloat16 G_WvT_hi[262144], G_WvT_lo[262144];   // [c'][c]
__device__ __nv_bfloat16 G_WpT_hi[524288], G_WpT_lo[524288];   // [b][c'][e]
__device__ float S_vinp[67108864];          // x @ Wv (fp32, conv branch)
__device__ float S_v[67108864];             // conv1 output scratch
__device__ float g_XtX[2 * 512 * 512];
__device__ float g_T1[2 * 512 * 512];
__device__ float g_T2[2 * 512 * 512];
__device__ float g_G[2 * 8 * 64 * 64];
__device__ float g_Att[2 * 8 * 64 * 64];
__device__ float g_NQ[2 * 512];
__device__ float g_NK[2 * 512];

// upper-triangle pairs of the 4x4 tile grid
__constant__ int c_pi10[10] = {0,0,0,0,1,1,1,2,2,3};
__constant__ int c_pj10[10] = {0,1,2,3,1,2,3,2,3,3};

// ===================== portable PTX helpers ===================================
__device__ __forceinline__ uint32_t smem_u32(const void* p) {
    uint32_t a;
    asm("{ .reg .u64 t; cvta.to.shared.u64 t, %1; cvt.u32.u64 %0, t; }" : "=r"(a) : "l"(p));
    return a;
}
__device__ __forceinline__ void cp16(uint32_t dst, const void* src) {
    asm volatile("cp.async.cg.shared.global [%0], [%1], 16;" :: "r"(dst), "l"(src) : "memory");
}
#define CP_COMMIT() asm volatile("cp.async.commit_group;" ::: "memory")
#define CP_WAIT(n)  asm volatile("cp.async.wait_group %0;" :: "n"(n) : "memory")

#define SWZ(o) ((uint32_t)(o) ^ ((((uint32_t)(o)) >> 3) & 0x70u))

__device__ __forceinline__ void ldsm4(uint32_t (&r)[4], uint32_t a) {
    asm volatile("ldmatrix.sync.aligned.m8n8.x4.shared.b16 {%0,%1,%2,%3}, [%4];"
        : "=r"(r[0]), "=r"(r[1]), "=r"(r[2]), "=r"(r[3]) : "r"(a));
}
__device__ __forceinline__ void mma16816(float (&c)[4], const uint32_t (&a)[4],
                                         const uint32_t* b) {
    asm volatile("mma.sync.aligned.m16n8k16.row.col.f32.bf16.bf16.f32 "
        "{%0,%1,%2,%3}, {%4,%5,%6,%7}, {%8,%9}, {%0,%1,%2,%3};"
        : "+f"(c[0]), "+f"(c[1]), "+f"(c[2]), "+f"(c[3])
        : "r"(a[0]), "r"(a[1]), "r"(a[2]), "r"(a[3]), "r"(b[0]), "r"(b[1]));
}

__device__ __forceinline__ uint32_t pack_hl(float v0, float v1, uint32_t& lo) {
    __nv_bfloat16 h0 = __float2bfloat16(v0), h1 = __float2bfloat16(v1);
    __nv_bfloat16 l0 = __float2bfloat16(v0 - __bfloat162float(h0));
    __nv_bfloat16 l1 = __float2bfloat16(v1 - __bfloat162float(h1));
    lo = (uint32_t)__bfloat16_as_ushort(l0) | ((uint32_t)__bfloat16_as_ushort(l1) << 16);
    return (uint32_t)__bfloat16_as_ushort(h0) | ((uint32_t)__bfloat16_as_ushort(h1) << 16);
}

// ===================== HMMA GEMM core v3 ======================================
// CTA tile 128x128, K-chunk 64 bf16 (128B SW128 rows). 512 threads,
// 16 warps in 4x4 grid, warp tile 32x32. 3-stage cp.async ring (192KB smem).
#define STAGE 65536u
#define MM_SMEM (1024 + 3 * 65536)

__device__ __forceinline__ void load_chunk(uint32_t st, int tid,
    const __nv_bfloat16* ah, const __nv_bfloat16* al, size_t lda,
    const __nv_bfloat16* bh, const __nv_bfloat16* bl, size_t ldb)
{
#pragma unroll
    for (int i = 0; i < 2; ++i) {
        int item = tid + 512 * i;             // 0..1023
        int rr = item >> 3, cc = item & 7;    // 128 rows x 8 x 16B
        uint32_t so = SWZ(rr * 128 + cc * 16);
        cp16(st + so,           ah + (size_t)rr * lda + cc * 8);
        cp16(st + 16384u + so,  al + (size_t)rr * lda + cc * 8);
        cp16(st + 32768u + so,  bh + (size_t)rr * ldb + cc * 8);
        cp16(st + 49152u + so,  bl + (size_t)rr * ldb + cc * 8);
    }
    CP_COMMIT();
}

__device__ void mm_loop(const __nv_bfloat16* Ahi, const __nv_bfloat16* Alo, size_t lda,
                        const __nv_bfloat16* Bhi, const __nv_bfloat16* Blo, size_t ldb,
                        int kiters, char* smem_raw, float (&acc)[2][4][4])
{
    const int tid = threadIdx.x, lane = tid & 31, wid = tid >> 5;
    const int wm = wid >> 2, wn = wid & 3;
    uint32_t sb = (smem_u32(smem_raw) + 1023u) & ~1023u;

    load_chunk(sb, tid, Ahi, Alo, lda, Bhi, Blo, ldb);
    if (kiters > 1)
        load_chunk(sb + STAGE, tid, Ahi + 64, Alo + 64, lda, Bhi + 64, Blo + 64, ldb);

    const int a_row = wm * 32 + (lane & 15);
    const int a_kb  = (lane >> 4) << 4;
    const int g     = lane >> 3;
    const int b_row = wn * 32 + ((g >> 1) << 3) + (lane & 7);
    const int b_kb  = (g & 1) << 4;

    uint32_t stage_of[3] = {sb, sb + STAGE, sb + 2 * STAGE};
    int cur = 0;

    for (int k = 0; k < kiters; ++k) {
        uint32_t st = stage_of[cur];
        if (k + 1 < kiters) CP_WAIT(1); else CP_WAIT(0);
        __syncthreads();
        if (k + 2 < kiters) {
            int nxt = cur + 2; if (nxt >= 3) nxt -= 3;
            load_chunk(stage_of[nxt], tid,
                       Ahi + (size_t)(k + 2) * 64, Alo + (size_t)(k + 2) * 64, lda,
                       Bhi + (size_t)(k + 2) * 64, Blo + (size_t)(k + 2) * 64, ldb);
        }
#pragma unroll
        for (int ks = 0; ks < 4; ++ks) {
            uint32_t ah[2][4], al[2][4];
#pragma unroll
            for (int mt = 0; mt < 2; ++mt) {
                uint32_t so = SWZ((a_row + mt * 16) * 128 + ks * 32 + a_kb);
                ldsm4(ah[mt], st + so);
                ldsm4(al[mt], st + 16384u + so);
            }
            uint32_t bh[2][4], bl[2][4];
#pragma unroll
            for (int p = 0; p < 2; ++p) {
                uint32_t so = SWZ((b_row + p * 16) * 128 + ks * 32 + b_kb);
                ldsm4(bh[p], st + 32768u + so);
                ldsm4(bl[p], st + 49152u + so);
            }
#pragma unroll
            for (int mt = 0; mt < 2; ++mt)
#pragma unroll
                for (int nt = 0; nt < 4; ++nt) {
                    const uint32_t* bhp = &bh[nt >> 1][(nt & 1) * 2];
                    const uint32_t* blp = &bl[nt >> 1][(nt & 1) * 2];
                    mma16816(acc[mt][nt], ah[mt], bhp);   // hi*hi
                    mma16816(acc[mt][nt], ah[mt], blp);   // hi*lo
                    mma16816(acc[mt][nt], al[mt], bhp);   // lo*hi
                }
        }
        if (++cur == 3) cur = 0;
    }
}

// ---------------- v_inp = X @ Wv ; v = v_inp * illu ---------------------------
// grid (4 n-tiles, 1024 m-tiles): CTAs sharing an A tile are adjacent -> L2 reuse
__global__ __launch_bounds__(512, 1) void k_mm_v(const float* __restrict__ illu)
{
    extern __shared__ char smem[];
    float acc[2][4][4] = {};
    const int n0 = blockIdx.x * 128;
    const size_t m0 = (size_t)blockIdx.y * 128;
    mm_loop(G_Xhi + m0 * 512, G_Xlo + m0 * 512, 512,
            G_WvT_hi + (size_t)n0 * 512, G_WvT_lo + (size_t)n0 * 512, 512,
            8, smem, acc);
    const int lane = threadIdx.x & 31, wid = threadIdx.x >> 5;
    const int wm = wid >> 2, wn = wid & 3;
#pragma unroll
    for (int mt = 0; mt < 2; ++mt)
#pragma unroll
        for (int nt = 0; nt < 4; ++nt) {
            size_t row = m0 + wm * 32 + mt * 16 + (lane >> 2);
            int col = n0 + wn * 32 + nt * 8 + (lane & 3) * 2;
#pragma unroll
            for (int h = 0; h < 2; ++h) {
                size_t o = (row + h * 8) * 512 + col;
                float v0 = acc[mt][nt][h * 2 + 0], v1 = acc[mt][nt][h * 2 + 1];
                *(float2*)(S_vinp + o) = make_float2(v0, v1);
                float2 il = *(const float2*)(illu + o);
                uint32_t lo, hi = pack_hl(v0 * il.x, v1 * il.y, lo);
                *(uint32_t*)(G_Vhi + o) = hi;
                *(uint32_t*)(G_Vlo + o) = lo;
            }
        }
}

// ---------------- XtX upper-triangle tiles (128x128), split-K atomics ---------
__global__ __launch_bounds__(512, 1) void k_mm_xtx()
{
    extern __shared__ char smem[];
    float acc[2][4][4] = {};
    const int pr = blockIdx.x;                  // 10 upper-tri pairs
    const int ks = blockIdx.y;                  // 16 K-splits of 4096 tokens
    const int b  = blockIdx.z;
    const size_t i0 = (size_t)c_pi10[pr] * 128, j0 = (size_t)c_pj10[pr] * 128;
    const int mirror = (i0 != j0);
    const __nv_bfloat16* Th = G_XThi + (size_t)b * 512 * 65536 + (size_t)ks * 4096;
    const __nv_bfloat16* Tl = G_XTlo + (size_t)b * 512 * 65536 + (size_t)ks * 4096;
    mm_loop(Th + i0 * 65536, Tl + i0 * 65536, 65536,
            Th + j0 * 65536, Tl + j0 * 65536, 65536,
            64, smem, acc);
    const int lane = threadIdx.x & 31, wid = threadIdx.x >> 5;
    const int wm = wid >> 2, wn = wid & 3;
    float* C = g_XtX + b * 262144;
#pragma unroll
    for (int mt = 0; mt < 2; ++mt)
#pragma unroll
        for (int nt = 0; nt < 4; ++nt) {
            int row = (int)i0 + wm * 32 + mt * 16 + (lane >> 2);
            int col = (int)j0 + wn * 32 + nt * 8 + (lane & 3) * 2;
#pragma unroll
            for (int h = 0; h < 2; ++h) {
                float v0 = acc[mt][nt][h * 2 + 0], v1 = acc[mt][nt][h * 2 + 1];
                int r = row + h * 8;
                atomicAdd(&C[r * 512 + col],     v0);
                atomicAdd(&C[r * 512 + col + 1], v1);
                if (mirror) {
                    atomicAdd(&C[col * 512 + r],       v0);
                    atomicAdd(&C[(col + 1) * 512 + r], v1);
                }
            }
        }
}

// ---------------- out = v @ WpEff^T + bp --------------------------------------
__global__ __launch_bounds__(512, 1) void k_mm_out(const float* __restrict__ bp,
                                                   float* __restrict__ out)
{
    extern __shared__ char smem[];
    float acc[2][4][4] = {};
    const int n0 = blockIdx.x * 128;
    const size_t m0 = (size_t)blockIdx.y * 128;
    const int b = (m0 >= (size_t)NTOK) ? 1 : 0;
    mm_loop(G_Vhi + m0 * 512, G_Vlo + m0 * 512, 512,
            G_WpT_hi + (size_t)b * 262144 + (size_t)n0 * 512,
            G_WpT_lo + (size_t)b * 262144 + (size_t)n0 * 512, 512,
            8, smem, acc);
    const int lane = threadIdx.x & 31, wid = threadIdx.x >> 5;
    const int wm = wid >> 2, wn = wid & 3;
#pragma unroll
    for (int mt = 0; mt < 2; ++mt)
#pragma unroll
        for (int nt = 0; nt < 4; ++nt) {
            size_t row = m0 + wm * 32 + mt * 16 + (lane >> 2);
            int col = n0 + wn * 32 + nt * 8 + (lane & 3) * 2;
            float2 bb = *(const float2*)(bp + col);
#pragma unroll
            for (int h = 0; h < 2; ++h) {
                size_t o = (row + h * 8) * 512 + col;
                *(float2*)(out + o) = make_float2(acc[mt][nt][h * 2 + 0] + bb.x,
                                                  acc[mt][nt][h * 2 + 1] + bb.y);
            }
        }
}

// ---------------- convert X -> bf16 hi/lo, row-major + transposed -------------
__global__ __launch_bounds__(256) void k_cvt_x(const float* __restrict__ X)
{
    __shared__ float tile[64][65];
    const int n0 = blockIdx.x * 64;
    const int c0 = blockIdx.y * 64;
    const int tid = threadIdx.x;
#pragma unroll
    for (int i = 0; i < 4; ++i) {
        int item = tid + 256 * i;
        int r = item >> 4, c4 = item & 15;
        float4 v = *(const float4*)(X + (size_t)(n0 + r) * 512 + c0 + c4 * 4);
        tile[r][c4 * 4 + 0] = v.x; tile[r][c4 * 4 + 1] = v.y;
        tile[r][c4 * 4 + 2] = v.z; tile[r][c4 * 4 + 3] = v.w;
        uint32_t l0, l1;
        uint32_t h0 = pack_hl(v.x, v.y, l0), h1 = pack_hl(v.z, v.w, l1);
        size_t o = (size_t)(n0 + r) * 512 + c0 + c4 * 4;
        *(uint2*)(G_Xhi + o) = make_uint2(h0, h1);
        *(uint2*)(G_Xlo + o) = make_uint2(l0, l1);
    }
    __syncthreads();
    const int b = n0 >> 16;
    const int nin0 = n0 & 65535;
#pragma unroll
    for (int i = 0; i < 4; ++i) {
        int item = tid + 256 * i;
        int cc = item >> 4, t4 = item & 15;
        float v0 = tile[t4 * 4 + 0][cc], v1 = tile[t4 * 4 + 1][cc];
        float v2 = tile[t4 * 4 + 2][cc], v3 = tile[t4 * 4 + 3][cc];
        uint32_t l0, l1;
        uint32_t h0 = pack_hl(v0, v1, l0), h1 = pack_hl(v2, v3, l1);
        size_t o = (size_t)b * 512 * 65536 + (size_t)(c0 + cc) * 65536 + nin0 + t4 * 4;
        *(uint2*)(G_XThi + o) = make_uint2(h0, h1);
        *(uint2*)(G_XTlo + o) = make_uint2(l0, l1);
    }
}

// ---------------- convert Wv -> WvT hi/lo -------------------------------------
__global__ void k_cvt_w(const float* __restrict__ Wv)
{
    int o = blockIdx.x * 256 + threadIdx.x;       // [cp][c]
    int cp = o >> 9, c = o & 511;
    float v = Wv[(size_t)c * 512 + cp];
    __nv_bfloat16 h = __float2bfloat16(v);
    G_WvT_hi[o] = h;
    G_WvT_lo[o] = __float2bfloat16(v - __bfloat162float(h));
}

// ---------------- zero accumulated buffers ------------------------------------
__global__ void k_zero()
{
    int i = blockIdx.x * 256 + threadIdx.x;
    if (i < 2 * 512 * 512) { g_XtX[i] = 0.f; g_T1[i] = 0.f; g_T2[i] = 0.f; }
    if (i < 2 * 8 * 64 * 64) g_G[i] = 0.f;
}

// ===================== fp32 mid-chain =========================================
__device__ __forceinline__ void sgemm_core(const float* __restrict__ A,
                                           const float* __restrict__ Bw,
                                           int lda, int ldb, int kiters,
                                           float (&acc)[8][8])
{
    __shared__ float As[8][128];
    __shared__ float Bs[8][128];
    const int tid = threadIdx.x;
    const int lr = tid >> 1, lc = (tid & 1) << 2;
    const int wr = tid >> 5, wc = (tid & 31) << 2;
    const int ty = tid >> 4, tx = tid & 15;
    for (int kt = 0; kt < kiters; ++kt) {
        float4 a = *(const float4*)(A + (size_t)lr * lda + (kt << 3) + lc);
        float4 b = *(const float4*)(Bw + (size_t)((kt << 3) + wr) * ldb + wc);
        __syncthreads();
        As[lc + 0][lr] = a.x; As[lc + 1][lr] = a.y;
        As[lc + 2][lr] = a.z; As[lc + 3][lr] = a.w;
        *(float4*)&Bs[wr][wc] = b;
        __syncthreads();
#pragma unroll
        for (int kk = 0; kk < 8; ++kk) {
            float4 a0 = *(const float4*)&As[kk][ty << 3];
            float4 a1 = *(const float4*)&As[kk][(ty << 3) + 4];
            float4 b0 = *(const float4*)&Bs[kk][tx << 3];
            float4 b1 = *(const float4*)&Bs[kk][(tx << 3) + 4];
            float ra[8] = {a0.x, a0.y, a0.z, a0.w, a1.x, a1.y, a1.z, a1.w};
            float rb[8] = {b0.x, b0.y, b0.z, b0.w, b1.x, b1.y, b1.z, b1.w};
#pragma unroll
            for (int i = 0; i < 8; ++i)
#pragma unroll
                for (int j = 0; j < 8; ++j)
                    acc[i][j] = fmaf(ra[i], rb[j], acc[i][j]);
        }
    }
}

__global__ __launch_bounds__(256) void k_T(const float* __restrict__ Wq,
                                           const float* __restrict__ Wk)
{
    float acc[8][8] = {};
    const int col0 = blockIdx.x << 7;
    const int row0 = blockIdx.y << 7;
    const int z = blockIdx.z;
    const int b = z >> 4, mat = (z >> 3) & 1, kc = z & 7;
    const float* A  = g_XtX + b * (512 * 512) + (size_t)row0 * 512 + kc * 64;
    const float* Wm = (mat ? Wk : Wq) + (size_t)(kc * 64) * 512 + col0;
    sgemm_core(A, Wm, 512, 512, 8, acc);
    float* T = (mat ? g_T2 : g_T1) + b * (512 * 512);
    const int ty = threadIdx.x >> 4, tx = threadIdx.x & 15;
#pragma unroll
    for (int i = 0; i < 8; ++i)
#pragma unroll
        for (int j = 0; j < 8; ++j)
            atomicAdd(&T[(row0 + (ty << 3) + i) * 512 + col0 + (tx << 3) + j], acc[i][j]);
}

__global__ void k_normsq(const float* __restrict__ Wq, const float* __restrict__ Wk)
{
    const int b = blockIdx.x, mat = blockIdx.y;
    const float* Wm = mat ? Wk : Wq;
    const float* T  = (mat ? g_T2 : g_T1) + b * (512 * 512);
    const int j = threadIdx.x;
    float acc = 0.f;
    for (int k = 0; k < 512; ++k)
        acc = fmaf(Wm[k * 512 + j], T[k * 512 + j], acc);
    (mat ? g_NK : g_NQ)[b * 512 + j] = acc;
}

__global__ __launch_bounds__(256) void k_G(const float* __restrict__ Wk)
{
    __shared__ float Ks[64][64];
    __shared__ float Ts[64][64];
    const int kc = blockIdx.x, h = blockIdx.y, b = blockIdx.z;
    const int tid = threadIdx.x;
    for (int idx = tid; idx < 4096; idx += 256) {
        int kk = idx >> 6, col = idx & 63;
        Ks[kk][col] = Wk[(size_t)(kc * 64 + kk) * 512 + h * 64 + col];
        Ts[kk][col] = g_T1[b * (512 * 512) + (size_t)(kc * 64 + kk) * 512 + h * 64 + col];
    }
    __syncthreads();
    const int ty = tid >> 4, tx = tid & 15;
    float acc[4][4] = {};
    for (int kk = 0; kk < 64; ++kk) {
        float a[4], bb[4];
#pragma unroll
        for (int i = 0; i < 4; ++i) a[i]  = Ks[kk][ty * 4 + i];
#pragma unroll
        for (int j = 0; j < 4; ++j) bb[j] = Ts[kk][tx * 4 + j];
#pragma unroll
        for (int i = 0; i < 4; ++i)
#pragma unroll
            for (int j = 0; j < 4; ++j)
                acc[i][j] = fmaf(a[i], bb[j], acc[i][j]);
    }
    float* Gp = g_G + ((size_t)(b * 8 + h) << 12);
#pragma unroll
    for (int i = 0; i < 4; ++i)
#pragma unroll
        for (int j = 0; j < 4; ++j)
            atomicAdd(&Gp[(ty * 4 + i) * 64 + tx * 4 + j], acc[i][j]);
}

__global__ void k_softmax(const float* __restrict__ rescale)
{
    const int bh = blockIdx.x;
    const int b = bh >> 3, h = bh & 7;
    const int d = threadIdx.x;
    __shared__ float rnq[64];
    rnq[d] = 1.f / fmaxf(sqrtf(g_NQ[b * 512 + h * 64 + d]), 1e-12f);
    __syncthreads();
    const float rk = rescale[h] / fmaxf(sqrtf(g_NK[b * 512 + h * 64 + d]), 1e-12f);
    const float* Grow = g_G + ((size_t)bh << 12) + d * 64;
    float* Arow = g_Att + ((size_t)bh << 12) + d * 64;
    float mx = -1e30f;
    for (int e = 0; e < 64; ++e) mx = fmaxf(mx, Grow[e] * rk * rnq[e]);
    float sum = 0.f;
    for (int e = 0; e < 64; ++e) {
        float ex = expf(Grow[e] * rk * rnq[e] - mx);
        Arow[e] = ex;
        sum += ex;
    }
    float inv = 1.f / sum;
    for (int e = 0; e < 64; ++e) Arow[e] *= inv;
}

// WpEffT[b][c'][e] = sum_d Att[b,h,d,e] * Wp[h*64+d][c']  (bf16 hi/lo out)
__global__ __launch_bounds__(256) void k_wpeff(const float* __restrict__ Wp)
{
    __shared__ float Atts[64][64];
    __shared__ float Wps[64][128];
    const int ct = blockIdx.x, h = blockIdx.y, b = blockIdx.z;
    const int tid = threadIdx.x;
    for (int idx = tid; idx < 4096; idx += 256)
        Atts[idx >> 6][idx & 63] = g_Att[((size_t)(b * 8 + h) << 12) + idx];
    for (int idx = tid; idx < 8192; idx += 256) {
        int dd = idx >> 7, cc = idx & 127;
        Wps[dd][cc] = Wp[(size_t)(h * 64 + dd) * 512 + ct * 128 + cc];
    }
    __syncthreads();
    const int ty = tid >> 4, tx = tid & 15;
    float acc[4][8] = {};
    for (int dd = 0; dd < 64; ++dd) {
        float a[4], bb[8];
#pragma unroll
        for (int i = 0; i < 4; ++i) a[i]  = Atts[dd][ty * 4 + i];
#pragma unroll
        for (int j = 0; j < 8; ++j) bb[j] = Wps[dd][tx * 8 + j];
#pragma unroll
        for (int i = 0; i < 4; ++i)
#pragma unroll
            for (int j = 0; j < 8; ++j)
                acc[i][j] = fmaf(a[i], bb[j], acc[i][j]);
    }
#pragma unroll
    for (int i = 0; i < 4; ++i)
#pragma unroll
        for (int j = 0; j < 8; ++j) {
            float v = acc[i][j];
            int e = h * 64 + ty * 4 + i;
            int cpg = ct * 128 + tx * 8 + j;
            size_t o = (size_t)b * 262144 + (size_t)cpg * 512 + e;
            __nv_bfloat16 hh = __float2bfloat16(v);
            G_WpT_hi[o] = hh;
            G_WpT_lo[o] = __float2bfloat16(v - __bfloat162float(hh));
        }
}

// ---------------- depthwise conv 3x3 (NHWC) + exact GELU ----------------------
__global__ void k_conv1(const float* __restrict__ cw)
{
    __shared__ float kw[256 * 9];
    const int cbase9 = ((blockIdx.x & 1) << 8) * 9;
    for (int t = threadIdx.x; t < 2304; t += 256) kw[t] = cw[cbase9 + t];
    __syncthreads();
    const int idx = blockIdx.x * 256 + threadIdx.x;
    const int x = (idx >> 9) & 255, y = (idx >> 17) & 255;
    const float* w = &kw[threadIdx.x * 9];
    float acc = 0.f;
#pragma unroll
    for (int dy = -1; dy <= 1; ++dy) {
        int yy = y + dy; if ((unsigned)yy > 255u) continue;
#pragma unroll
        for (int dx = -1; dx <= 1; ++dx) {
            int xx = x + dx; if ((unsigned)xx > 255u) continue;
            acc = fmaf(S_vinp[idx + ((dy << 8) + dx) * 512], w[(dy + 1) * 3 + dx + 1], acc);
        }
    }
    S_v[idx] = 0.5f * acc * (1.f + erff(acc * 0.70710678118654752f));
}

__global__ void k_conv2(const float* __restrict__ cw, float* __restrict__ out)
{
    __shared__ float kw[256 * 9];
    const int cbase9 = ((blockIdx.x & 1) << 8) * 9;
    for (int t = threadIdx.x; t < 2304; t += 256) kw[t] = cw[cbase9 + t];
    __syncthreads();
    const int idx = blockIdx.x * 256 + threadIdx.x;
    const int x = (idx >> 9) & 255, y = (idx >> 17) & 255;
    const float* w = &kw[threadIdx.x * 9];
    float acc = 0.f;
#pragma unroll
    for (int dy = -1; dy <= 1; ++dy) {
        int yy = y + dy; if ((unsigned)yy > 255u) continue;
#pragma unroll
        for (int dx = -1; dx <= 1; ++dx) {
            int xx = x + dx; if ((unsigned)xx > 255u) continue;
            acc = fmaf(S_v[idx + ((dy << 8) + dx) * 512], w[(dy + 1) * 3 + dx + 1], acc);
        }
    }
    out[idx] += acc;
}

// ---------------- launcher -----------------------------------------------------
extern "C" void kernel_launch(void* const* d_in, const int* in_sizes, int n_in,
                              void* d_out, int out_size)
{
    const float* x    = (const float*)d_in[0];
    const float* illu = (const float*)d_in[1];
    const float* Wq   = (const float*)d_in[2];
    const float* Wk   = (const float*)d_in[3];
    const float* Wv   = (const float*)d_in[4];
    const float* resc = (const float*)d_in[5];
    const float* Wp   = (const float*)d_in[6];
    const float* bp   = (const float*)d_in[7];
    const float* cw1  = (const float*)d_in[8];
    const float* cw2  = (const float*)d_in[9];
    float* out = (float*)d_out;

    cudaFuncSetAttribute(k_mm_v,   cudaFuncAttributeMaxDynamicSharedMemorySize, MM_SMEM);
    cudaFuncSetAttribute(k_mm_xtx, cudaFuncAttributeMaxDynamicSharedMemorySize, MM_SMEM);
    cudaFuncSetAttribute(k_mm_out, cudaFuncAttributeMaxDynamicSharedMemorySize, MM_SMEM);

    k_zero<<<2048, 256>>>();
    k_cvt_x<<<dim3(2048, 8), 256>>>(x);
    k_cvt_w<<<1024, 256>>>(Wv);
    k_mm_v<<<dim3(4, 1024), 512, MM_SMEM>>>(illu);
    k_mm_xtx<<<dim3(10, 16, 2), 512, MM_SMEM>>>();
    k_T<<<dim3(4, 4, 32), 256>>>(Wq, Wk);
    k_normsq<<<dim3(2, 2), 512>>>(Wq, Wk);
    k_G<<<dim3(8, 8, 2), 256>>>(Wk);
    k_softmax<<<16, 64>>>(resc);
    k_wpeff<<<dim3(4, 8, 2), 256>>>(Wp);
    k_mm_out<<<dim3(4, 1024), 512, MM_SMEM>>>(bp, out);
    k_conv1<<<262144, 256>>>(cw1);
    k_conv2<<<262144, 256>>>(cw2, out);
}